// round 2
// baseline (speedup 1.0000x reference)
#include <cuda_runtime.h>
#include <math.h>

#define SEQ 512
#define BSZ 64
#define INP 512
#define HID 1024
#define NCTA 128                       // 16 j-chunks x 8 k-chunks
#define SW_STRIDE 72                   // floats per k-row of W tile (64 j + pad)
#define SH_STRIDE 66                   // ulls per k-row of h tile (64 b + pad)
#define SMEM2 (128 * SW_STRIDE * 4 + 128 * SH_STRIDE * 8)

typedef unsigned long long ull;

__device__ unsigned g_cnt[SEQ];

__global__ void zero_cnt_kernel() { g_cnt[threadIdx.x] = 0u; }

__device__ __forceinline__ ull ffma2(ull a, ull b, ull c) {
    ull d;
    asm("fma.rn.f32x2 %0, %1, %2, %3;" : "=l"(d) : "l"(a), "l"(b), "l"(c));
    return d;
}
__device__ __forceinline__ ull dup2(float x) {
    ull r;
    asm("mov.b64 %0, {%1, %1};" : "=l"(r) : "r"(__float_as_uint(x)));
    return r;
}

// ---------------------------------------------------------------------------
// Kernel 1: C[m][n] = sum_k A[m][k]*W[n][k] + b_ih[n] + b_hh[n]   (FFMA2)
// A = x_in (32768 x 512), W = W_ih (1024 x 512), C = d_out (32768 x 1024)
// Tile 64x64x16, 128 threads, thread tile 8m x 4n  (m paired for f32x2).
// ---------------------------------------------------------------------------
__global__ __launch_bounds__(128) void gemm_xw_kernel(
    const float* __restrict__ A,
    const float* __restrict__ W,
    const float* __restrict__ b_ih,
    const float* __restrict__ b_hh,
    float* __restrict__ C)
{
    __shared__ float sA[16][68];   // [k][m]
    __shared__ float sB[16][68];   // [k][n]

    const int t  = threadIdx.x;
    const int n0 = blockIdx.x * 64;
    const int m0 = blockIdx.y * 64;
    const int tx = t & 15;     // n = n0 + 4*tx + j
    const int ty = t >> 4;     // m = m0 + 8*ty + i
    const int lr = t >> 1;     // load row (0..63)
    const int lk = (t & 1) * 8;

    ull acc[4][4];             // [m-pair][n]
#pragma unroll
    for (int i = 0; i < 4; ++i)
#pragma unroll
        for (int j = 0; j < 4; ++j) acc[i][j] = 0ull;

    const float* Arow = A + (size_t)(m0 + lr) * INP + lk;
    const float* Wrow = W + (size_t)(n0 + lr) * INP + lk;

    for (int k0 = 0; k0 < INP; k0 += 16) {
        float4 a0 = *(const float4*)(Arow + k0);
        float4 a1 = *(const float4*)(Arow + k0 + 4);
        float4 w0 = *(const float4*)(Wrow + k0);
        float4 w1 = *(const float4*)(Wrow + k0 + 4);
        __syncthreads();
        sA[lk + 0][lr] = a0.x; sA[lk + 1][lr] = a0.y;
        sA[lk + 2][lr] = a0.z; sA[lk + 3][lr] = a0.w;
        sA[lk + 4][lr] = a1.x; sA[lk + 5][lr] = a1.y;
        sA[lk + 6][lr] = a1.z; sA[lk + 7][lr] = a1.w;
        sB[lk + 0][lr] = w0.x; sB[lk + 1][lr] = w0.y;
        sB[lk + 2][lr] = w0.z; sB[lk + 3][lr] = w0.w;
        sB[lk + 4][lr] = w1.x; sB[lk + 5][lr] = w1.y;
        sB[lk + 6][lr] = w1.z; sB[lk + 7][lr] = w1.w;
        __syncthreads();
#pragma unroll
        for (int k = 0; k < 16; ++k) {
            const ull* arow = (const ull*)&sA[k][ty * 8];
            ull am0 = arow[0], am1 = arow[1], am2 = arow[2], am3 = arow[3];
            float4 bv = *(const float4*)&sB[k][tx * 4];
            ull bn0 = dup2(bv.x), bn1 = dup2(bv.y);
            ull bn2 = dup2(bv.z), bn3 = dup2(bv.w);
            acc[0][0] = ffma2(am0, bn0, acc[0][0]);
            acc[0][1] = ffma2(am0, bn1, acc[0][1]);
            acc[0][2] = ffma2(am0, bn2, acc[0][2]);
            acc[0][3] = ffma2(am0, bn3, acc[0][3]);
            acc[1][0] = ffma2(am1, bn0, acc[1][0]);
            acc[1][1] = ffma2(am1, bn1, acc[1][1]);
            acc[1][2] = ffma2(am1, bn2, acc[1][2]);
            acc[1][3] = ffma2(am1, bn3, acc[1][3]);
            acc[2][0] = ffma2(am2, bn0, acc[2][0]);
            acc[2][1] = ffma2(am2, bn1, acc[2][1]);
            acc[2][2] = ffma2(am2, bn2, acc[2][2]);
            acc[2][3] = ffma2(am2, bn3, acc[2][3]);
            acc[3][0] = ffma2(am3, bn0, acc[3][0]);
            acc[3][1] = ffma2(am3, bn1, acc[3][1]);
            acc[3][2] = ffma2(am3, bn2, acc[3][2]);
            acc[3][3] = ffma2(am3, bn3, acc[3][3]);
        }
    }

    float4 bi = *(const float4*)(b_ih + n0 + tx * 4);
    float4 bh = *(const float4*)(b_hh + n0 + tx * 4);
    float4 bias;
    bias.x = bi.x + bh.x; bias.y = bi.y + bh.y;
    bias.z = bi.z + bh.z; bias.w = bi.w + bh.w;

#pragma unroll
    for (int i = 0; i < 8; ++i) {
        const int mp = i >> 1;
        const int sel = i & 1;
        float2 a0 = *(float2*)&acc[mp][0];
        float2 a1 = *(float2*)&acc[mp][1];
        float2 a2 = *(float2*)&acc[mp][2];
        float2 a3 = *(float2*)&acc[mp][3];
        float4 o;
        o.x = (sel ? a0.y : a0.x) + bias.x;
        o.y = (sel ? a1.y : a1.x) + bias.y;
        o.z = (sel ? a2.y : a2.x) + bias.z;
        o.w = (sel ? a3.y : a3.x) + bias.w;
        *(float4*)&C[(size_t)(m0 + ty * 8 + i) * HID + n0 + tx * 4] = o;
    }
}

// ---------------------------------------------------------------------------
// Kernel 2: persistent recurrence with FFMA2.
// CTA (jc,kc): W_hh[jc*64..+64) x [kc*128..+128) cached in smem (k-major).
// 256 threads = 2 groups of 128; group g handles k-half g. Both groups
// compute a 4b x 8j thread tile over 64b x 64j; partials reduced through
// smem, then group 0 atomically adds into the pre-activation buffer.
// ---------------------------------------------------------------------------
__global__ __launch_bounds__(256) void rnn_step_kernel(
    const float* __restrict__ Whh,   // 1024 x 1024
    float* __restrict__ out)         // (64, 512, 1024) pre-seeded with xw+bias
{
    extern __shared__ float smem[];
    float* sW = smem;                             // [128][SW_STRIDE] floats
    ull*   sh2 = (ull*)(smem + 128 * SW_STRIDE);  // [128][SH_STRIDE] dup pairs

    const int t  = threadIdx.x;
    const int jc = blockIdx.x & 15;   // 0..15 (64 j each)
    const int kc = blockIdx.x >> 4;   // 0..7  (128 k each)

    // One-time W tile load, transposed to k-major.
    {
        const int j  = t >> 2;              // 0..63
        const int kq = (t & 3) * 32;        // 0,32,64,96
        const float* src = Whh + (size_t)(jc * 64 + j) * HID + kc * 128 + kq;
#pragma unroll
        for (int kk = 0; kk < 32; kk += 4) {
            float4 v = *(const float4*)(src + kk);
            sW[(kq + kk + 0) * SW_STRIDE + j] = v.x;
            sW[(kq + kk + 1) * SW_STRIDE + j] = v.y;
            sW[(kq + kk + 2) * SW_STRIDE + j] = v.z;
            sW[(kq + kk + 3) * SW_STRIDE + j] = v.w;
        }
    }
    __syncthreads();

    const int grp = t >> 7;            // k-half
    const int tg  = t & 127;
    const int tb4 = (tg & 15) * 4;     // base b of thread tile
    const int tj  = tg >> 4;           // 0..7 -> j_local = tj*8
    const int kbase = grp * 64;

    const int fb = t >> 2;             // fill: b (0..63)
    const int fk = (t & 3) * 32;       // fill: k base

    for (int s = 1; s < SEQ; ++s) {
        if (s >= 2) {
            if (t == 0) {
                volatile unsigned* p = &g_cnt[s - 1];
                while (*p != (unsigned)NCTA) __nanosleep(32);
                __threadfence();
            }
            __syncthreads();
        }

        // Fill sh2[k][b] = dup2(tanh(pre-act[b][s-1][kc*128+k])).
        {
            const float* src = out + ((size_t)(fb * SEQ + (s - 1))) * HID
                                   + kc * 128 + fk;
#pragma unroll
            for (int kk = 0; kk < 32; kk += 4) {
                float4 v = __ldcg((const float4*)(src + kk));
                sh2[(fk + kk + 0) * SH_STRIDE + fb] = dup2(tanhf(v.x));
                sh2[(fk + kk + 1) * SH_STRIDE + fb] = dup2(tanhf(v.y));
                sh2[(fk + kk + 2) * SH_STRIDE + fb] = dup2(tanhf(v.z));
                sh2[(fk + kk + 3) * SH_STRIDE + fb] = dup2(tanhf(v.w));
            }
        }
        __syncthreads();

        ull acc[4][4];                 // [b][j-pair]
#pragma unroll
        for (int i = 0; i < 4; ++i)
#pragma unroll
            for (int j = 0; j < 4; ++j) acc[i][j] = 0ull;

        const ull* hbase = sh2 + (size_t)kbase * SH_STRIDE + tb4;
        const ull* wbase = (const ull*)(sW + (size_t)kbase * SW_STRIDE) + tj * 4;

#pragma unroll 4
        for (int k = 0; k < 64; ++k) {
            const ull* hp = hbase + (size_t)k * SH_STRIDE;
            const ull* wp = wbase + (size_t)k * (SW_STRIDE / 2);
            ull h0 = hp[0], h1 = hp[1], h2 = hp[2], h3 = hp[3];
            ull w0 = wp[0], w1 = wp[1], w2 = wp[2], w3 = wp[3];
            acc[0][0] = ffma2(h0, w0, acc[0][0]);
            acc[0][1] = ffma2(h0, w1, acc[0][1]);
            acc[0][2] = ffma2(h0, w2, acc[0][2]);
            acc[0][3] = ffma2(h0, w3, acc[0][3]);
            acc[1][0] = ffma2(h1, w0, acc[1][0]);
            acc[1][1] = ffma2(h1, w1, acc[1][1]);
            acc[1][2] = ffma2(h1, w2, acc[1][2]);
            acc[1][3] = ffma2(h1, w3, acc[1][3]);
            acc[2][0] = ffma2(h2, w0, acc[2][0]);
            acc[2][1] = ffma2(h2, w1, acc[2][1]);
            acc[2][2] = ffma2(h2, w2, acc[2][2]);
            acc[2][3] = ffma2(h2, w3, acc[2][3]);
            acc[3][0] = ffma2(h3, w0, acc[3][0]);
            acc[3][1] = ffma2(h3, w1, acc[3][1]);
            acc[3][2] = ffma2(h3, w2, acc[3][2]);
            acc[3][3] = ffma2(h3, w3, acc[3][3]);
        }

        __syncthreads();               // everyone done reading sh2

        ull* red = sh2;                // reuse h buffer for reduction
        if (grp == 1) {
            ull* dst = red + (size_t)tg * 16;
#pragma unroll
            for (int i = 0; i < 4; ++i)
#pragma unroll
                for (int j = 0; j < 4; ++j) dst[i * 4 + j] = acc[i][j];
        }
        __syncthreads();
        if (grp == 0) {
            const ull* src = red + (size_t)tg * 16;
#pragma unroll
            for (int i = 0; i < 4; ++i) {
                const int b = tb4 + i;
                float* row = out + ((size_t)(b * SEQ + s)) * HID
                                 + jc * 64 + tj * 8;
#pragma unroll
                for (int j = 0; j < 4; ++j) {
                    float2 mine = *(float2*)&acc[i][j];
                    float2 oth  = *(const float2*)&src[i * 4 + j];
                    atomicAdd(row + j * 2 + 0, mine.x + oth.x);
                    atomicAdd(row + j * 2 + 1, mine.y + oth.y);
                }
            }
            __threadfence();
        }
        __syncthreads();
        if (t == 0 && s < SEQ - 1) atomicAdd(&g_cnt[s], 1u);
    }
}

// ---------------------------------------------------------------------------
// Kernel 3: elementwise tanh over the whole output buffer.
// ---------------------------------------------------------------------------
__global__ __launch_bounds__(256) void tanh_kernel(float* __restrict__ out) {
    size_t i = ((size_t)blockIdx.x * blockDim.x + threadIdx.x) * 4;
    float4 v = *(float4*)(out + i);
    v.x = tanhf(v.x); v.y = tanhf(v.y);
    v.z = tanhf(v.z); v.w = tanhf(v.w);
    *(float4*)(out + i) = v;
}

extern "C" void kernel_launch(void* const* d_in, const int* in_sizes, int n_in,
                              void* d_out, int out_size) {
    const float* x   = (const float*)d_in[0];   // (64, 512, 512)
    const float* Wih = (const float*)d_in[1];   // (1024, 512)
    const float* Whh = (const float*)d_in[2];   // (1024, 1024)
    const float* bih = (const float*)d_in[3];   // (1024,)
    const float* bhh = (const float*)d_in[4];   // (1024,)
    float* out = (float*)d_out;                 // (64, 512, 1024)

    cudaFuncSetAttribute(rnn_step_kernel,
                         cudaFuncAttributeMaxDynamicSharedMemorySize, SMEM2);

    zero_cnt_kernel<<<1, SEQ>>>();

    dim3 g1(HID / 64, (BSZ * SEQ) / 64);
    gemm_xw_kernel<<<g1, 128>>>(x, Wih, bih, bhh, out);

    rnn_step_kernel<<<NCTA, 256, SMEM2>>>(Whh, out);

    tanh_kernel<<<(BSZ * SEQ * HID) / (256 * 4), 256>>>(out);
}

// round 4
// speedup vs baseline: 1.8103x; 1.8103x over previous
#include <cuda_runtime.h>
#include <math.h>

#define SEQ 512
#define BSZ 64
#define INP 512
#define HID 1024
#define NCTA 128                 // 16 j-chunks x 8 k-chunks
#define SW_STRIDE 72             // floats per k-row of W tile (64 j + pad)
#define SH_STRIDE 68             // floats per k-row of h tile (64 b + pad)
#define SMEM2 ((128 * SW_STRIDE + 128 * SH_STRIDE) * 4)

typedef unsigned long long ull;

__device__ unsigned g_cnt[SEQ];

__global__ void zero_cnt_kernel() { g_cnt[threadIdx.x] = 0u; }

__device__ __forceinline__ ull ffma2(ull a, ull b, ull c) {
    ull d;
    asm("fma.rn.f32x2 %0, %1, %2, %3;" : "=l"(d) : "l"(a), "l"(b), "l"(c));
    return d;
}
__device__ __forceinline__ ull dup2(float x) {
    ull r;
    asm("mov.b64 %0, {%1, %1};" : "=l"(r) : "r"(__float_as_uint(x)));
    return r;
}
__device__ __forceinline__ void red_add_v4(float* p, float a, float b,
                                           float c, float d) {
    asm volatile("red.global.add.v4.f32 [%0], {%1, %2, %3, %4};"
                 :: "l"(p), "f"(a), "f"(b), "f"(c), "f"(d) : "memory");
}

// ---------------------------------------------------------------------------
// Kernel 1: C[m][n] = sum_k A[m][k]*W[n][k] + b_ih[n] + b_hh[n]   (FFMA2)
// Tile 64x64x16, 128 threads, thread tile 8m x 4n (m paired for f32x2).
// ---------------------------------------------------------------------------
__global__ __launch_bounds__(128) void gemm_xw_kernel(
    const float* __restrict__ A,
    const float* __restrict__ W,
    const float* __restrict__ b_ih,
    const float* __restrict__ b_hh,
    float* __restrict__ C)
{
    __shared__ float sA[16][68];   // [k][m]
    __shared__ float sB[16][68];   // [k][n]

    const int t  = threadIdx.x;
    const int n0 = blockIdx.x * 64;
    const int m0 = blockIdx.y * 64;
    const int tx = t & 15;
    const int ty = t >> 4;
    const int lr = t >> 1;
    const int lk = (t & 1) * 8;

    ull acc[4][4];
#pragma unroll
    for (int i = 0; i < 4; ++i)
#pragma unroll
        for (int j = 0; j < 4; ++j) acc[i][j] = 0ull;

    const float* Arow = A + (size_t)(m0 + lr) * INP + lk;
    const float* Wrow = W + (size_t)(n0 + lr) * INP + lk;

    for (int k0 = 0; k0 < INP; k0 += 16) {
        float4 a0 = *(const float4*)(Arow + k0);
        float4 a1 = *(const float4*)(Arow + k0 + 4);
        float4 w0 = *(const float4*)(Wrow + k0);
        float4 w1 = *(const float4*)(Wrow + k0 + 4);
        __syncthreads();
        sA[lk + 0][lr] = a0.x; sA[lk + 1][lr] = a0.y;
        sA[lk + 2][lr] = a0.z; sA[lk + 3][lr] = a0.w;
        sA[lk + 4][lr] = a1.x; sA[lk + 5][lr] = a1.y;
        sA[lk + 6][lr] = a1.z; sA[lk + 7][lr] = a1.w;
        sB[lk + 0][lr] = w0.x; sB[lk + 1][lr] = w0.y;
        sB[lk + 2][lr] = w0.z; sB[lk + 3][lr] = w0.w;
        sB[lk + 4][lr] = w1.x; sB[lk + 5][lr] = w1.y;
        sB[lk + 6][lr] = w1.z; sB[lk + 7][lr] = w1.w;
        __syncthreads();
#pragma unroll
        for (int k = 0; k < 16; ++k) {
            const ull* arow = (const ull*)&sA[k][ty * 8];
            ull am0 = arow[0], am1 = arow[1], am2 = arow[2], am3 = arow[3];
            float4 bv = *(const float4*)&sB[k][tx * 4];
            ull bn0 = dup2(bv.x), bn1 = dup2(bv.y);
            ull bn2 = dup2(bv.z), bn3 = dup2(bv.w);
            acc[0][0] = ffma2(am0, bn0, acc[0][0]);
            acc[0][1] = ffma2(am0, bn1, acc[0][1]);
            acc[0][2] = ffma2(am0, bn2, acc[0][2]);
            acc[0][3] = ffma2(am0, bn3, acc[0][3]);
            acc[1][0] = ffma2(am1, bn0, acc[1][0]);
            acc[1][1] = ffma2(am1, bn1, acc[1][1]);
            acc[1][2] = ffma2(am1, bn2, acc[1][2]);
            acc[1][3] = ffma2(am1, bn3, acc[1][3]);
            acc[2][0] = ffma2(am2, bn0, acc[2][0]);
            acc[2][1] = ffma2(am2, bn1, acc[2][1]);
            acc[2][2] = ffma2(am2, bn2, acc[2][2]);
            acc[2][3] = ffma2(am2, bn3, acc[2][3]);
            acc[3][0] = ffma2(am3, bn0, acc[3][0]);
            acc[3][1] = ffma2(am3, bn1, acc[3][1]);
            acc[3][2] = ffma2(am3, bn2, acc[3][2]);
            acc[3][3] = ffma2(am3, bn3, acc[3][3]);
        }
    }

    float4 bi = *(const float4*)(b_ih + n0 + tx * 4);
    float4 bh = *(const float4*)(b_hh + n0 + tx * 4);
    float4 bias;
    bias.x = bi.x + bh.x; bias.y = bi.y + bh.y;
    bias.z = bi.z + bh.z; bias.w = bi.w + bh.w;

#pragma unroll
    for (int i = 0; i < 8; ++i) {
        const int mp = i >> 1;
        const int sel = i & 1;
        float2 a0 = *(float2*)&acc[mp][0];
        float2 a1 = *(float2*)&acc[mp][1];
        float2 a2 = *(float2*)&acc[mp][2];
        float2 a3 = *(float2*)&acc[mp][3];
        float4 o;
        o.x = (sel ? a0.y : a0.x) + bias.x;
        o.y = (sel ? a1.y : a1.x) + bias.y;
        o.z = (sel ? a2.y : a2.x) + bias.z;
        o.w = (sel ? a3.y : a3.x) + bias.w;
        *(float4*)&C[(size_t)(m0 + ty * 8 + i) * HID + n0 + tx * 4] = o;
    }
}

// ---------------------------------------------------------------------------
// Kernel 2: persistent recurrence (R1 skeleton, FFMA2 math, red.v4 output).
// CTA (jc,kc): W_hh[jc*64..+64) x [kc*128..+128) cached in smem (k-major).
// 128 threads, thread tile 4b x 8j (j paired for f32x2; W pairs natural).
// ---------------------------------------------------------------------------
__global__ __launch_bounds__(128) void rnn_step_kernel(
    const float* __restrict__ Whh,   // 1024 x 1024
    float* __restrict__ out)         // (64, 512, 1024) pre-seeded with xw+bias
{
    extern __shared__ float smem[];
    float* sW = smem;                      // [128][SW_STRIDE]
    float* sh = smem + 128 * SW_STRIDE;    // [128][SH_STRIDE]

    const int t  = threadIdx.x;
    const int jc = blockIdx.x & 15;   // 0..15 (64 j each)
    const int kc = blockIdx.x >> 4;   // 0..7  (128 k each)

    // One-time W tile load, transposed to k-major.
    {
        const int j  = t >> 1;
        const int kh = (t & 1) * 64;
        const float* src = Whh + (size_t)(jc * 64 + j) * HID + kc * 128 + kh;
#pragma unroll
        for (int kk = 0; kk < 64; kk += 4) {
            float4 v = *(const float4*)(src + kk);
            sW[(kh + kk + 0) * SW_STRIDE + j] = v.x;
            sW[(kh + kk + 1) * SW_STRIDE + j] = v.y;
            sW[(kh + kk + 2) * SW_STRIDE + j] = v.z;
            sW[(kh + kk + 3) * SW_STRIDE + j] = v.w;
        }
    }
    __syncthreads();

    const int tb4 = (t & 15) * 4;     // base b of thread tile
    const int tj8 = (t >> 4) * 8;     // base j of thread tile (4 pairs)
    const int bload  = t >> 1;        // fill: b (0..63)
    const int khload = (t & 1) * 64;  // fill: k base

    for (int s = 1; s < SEQ; ++s) {
        if (s >= 2) {
            if (t == 0) {
                volatile unsigned* p = &g_cnt[s - 1];
                while (*p != (unsigned)NCTA) __nanosleep(32);
                __threadfence();
            }
            __syncthreads();
        }

        // Fill sh[k][b] = tanh(pre-act[b][s-1][kc*128+k]).
        {
            const float* src = out + ((size_t)(bload * SEQ + (s - 1))) * HID
                                   + kc * 128 + khload;
#pragma unroll
            for (int kk = 0; kk < 64; kk += 4) {
                float4 v = __ldcg((const float4*)(src + kk));
                sh[(khload + kk + 0) * SH_STRIDE + bload] = tanhf(v.x);
                sh[(khload + kk + 1) * SH_STRIDE + bload] = tanhf(v.y);
                sh[(khload + kk + 2) * SH_STRIDE + bload] = tanhf(v.z);
                sh[(khload + kk + 3) * SH_STRIDE + bload] = tanhf(v.w);
            }
        }
        __syncthreads();

        ull acc[4][4];                 // [b][j-pair]
#pragma unroll
        for (int i = 0; i < 4; ++i)
#pragma unroll
            for (int j = 0; j < 4; ++j) acc[i][j] = 0ull;

        const float* hbase = sh + tb4;
        const float* wbase = sW + tj8;

#pragma unroll 4
        for (int k = 0; k < 128; ++k) {
            float4 hv = *(const float4*)(hbase + (size_t)k * SH_STRIDE);
            ulonglong2 wA = *(const ulonglong2*)(wbase + (size_t)k * SW_STRIDE);
            ulonglong2 wB = *(const ulonglong2*)(wbase + (size_t)k * SW_STRIDE + 4);
            ull h0 = dup2(hv.x), h1 = dup2(hv.y);
            ull h2 = dup2(hv.z), h3 = dup2(hv.w);
            acc[0][0] = ffma2(h0, wA.x, acc[0][0]);
            acc[0][1] = ffma2(h0, wA.y, acc[0][1]);
            acc[0][2] = ffma2(h0, wB.x, acc[0][2]);
            acc[0][3] = ffma2(h0, wB.y, acc[0][3]);
            acc[1][0] = ffma2(h1, wA.x, acc[1][0]);
            acc[1][1] = ffma2(h1, wA.y, acc[1][1]);
            acc[1][2] = ffma2(h1, wB.x, acc[1][2]);
            acc[1][3] = ffma2(h1, wB.y, acc[1][3]);
            acc[2][0] = ffma2(h2, wA.x, acc[2][0]);
            acc[2][1] = ffma2(h2, wA.y, acc[2][1]);
            acc[2][2] = ffma2(h2, wB.x, acc[2][2]);
            acc[2][3] = ffma2(h2, wB.y, acc[2][3]);
            acc[3][0] = ffma2(h3, wA.x, acc[3][0]);
            acc[3][1] = ffma2(h3, wA.y, acc[3][1]);
            acc[3][2] = ffma2(h3, wB.x, acc[3][2]);
            acc[3][3] = ffma2(h3, wB.y, acc[3][3]);
        }

        // Vectorized reduction into the pre-act buffer for step s.
#pragma unroll
        for (int i = 0; i < 4; ++i) {
            const int b = tb4 + i;
            float* row = out + ((size_t)(b * SEQ + s)) * HID + jc * 64 + tj8;
            float2 a0 = *(float2*)&acc[i][0];
            float2 a1 = *(float2*)&acc[i][1];
            float2 a2 = *(float2*)&acc[i][2];
            float2 a3 = *(float2*)&acc[i][3];
            red_add_v4(row,     a0.x, a0.y, a1.x, a1.y);
            red_add_v4(row + 4, a2.x, a2.y, a3.x, a3.y);
        }

        __threadfence();
        __syncthreads();
        if (t == 0 && s < SEQ - 1) atomicAdd(&g_cnt[s], 1u);
    }
}

// ---------------------------------------------------------------------------
// Kernel 3: elementwise tanh over the whole output buffer.
// ---------------------------------------------------------------------------
__global__ __launch_bounds__(256) void tanh_kernel(float* __restrict__ out) {
    size_t i = ((size_t)blockIdx.x * blockDim.x + threadIdx.x) * 4;
    float4 v = *(float4*)(out + i);
    v.x = tanhf(v.x); v.y = tanhf(v.y);
    v.z = tanhf(v.z); v.w = tanhf(v.w);
    *(float4*)(out + i) = v;
}

extern "C" void kernel_launch(void* const* d_in, const int* in_sizes, int n_in,
                              void* d_out, int out_size) {
    const float* x   = (const float*)d_in[0];   // (64, 512, 512)
    const float* Wih = (const float*)d_in[1];   // (1024, 512)
    const float* Whh = (const float*)d_in[2];   // (1024, 1024)
    const float* bih = (const float*)d_in[3];   // (1024,)
    const float* bhh = (const float*)d_in[4];   // (1024,)
    float* out = (float*)d_out;                 // (64, 512, 1024)

    cudaFuncSetAttribute(rnn_step_kernel,
                         cudaFuncAttributeMaxDynamicSharedMemorySize, SMEM2);

    zero_cnt_kernel<<<1, SEQ>>>();

    dim3 g1(HID / 64, (BSZ * SEQ) / 64);
    gemm_xw_kernel<<<g1, 128>>>(x, Wih, bih, bhh, out);

    rnn_step_kernel<<<NCTA, 128, SMEM2>>>(Whh, out);

    tanh_kernel<<<(BSZ * SEQ * HID) / (256 * 4), 256>>>(out);
}

// round 5
// speedup vs baseline: 2.1191x; 1.1706x over previous
#include <cuda_runtime.h>
#include <math.h>

#define SEQ 512
#define BSZ 64
#define INP 512
#define HID 1024
#define NCTA 128                 // 16 j-chunks x 8 k-chunks
#define SW_STRIDE 72             // floats per k-row of W tile (64 j + pad)
#define SH_STRIDE 68             // floats per k-row of h tile (64 b + pad)
#define SMEM2 ((128 * SW_STRIDE + 128 * SH_STRIDE) * 4)

typedef unsigned long long ull;

__device__ unsigned g_cnt[SEQ];

__global__ void zero_cnt_kernel() { g_cnt[threadIdx.x] = 0u; }

__device__ __forceinline__ ull ffma2(ull a, ull b, ull c) {
    ull d;
    asm("fma.rn.f32x2 %0, %1, %2, %3;" : "=l"(d) : "l"(a), "l"(b), "l"(c));
    return d;
}
__device__ __forceinline__ ull dup2(float x) {
    ull r;
    asm("mov.b64 %0, {%1, %1};" : "=l"(r) : "r"(__float_as_uint(x)));
    return r;
}
__device__ __forceinline__ void red_add_v4(float* p, float a, float b,
                                           float c, float d) {
    asm volatile("red.global.add.v4.f32 [%0], {%1, %2, %3, %4};"
                 :: "l"(p), "f"(a), "f"(b), "f"(c), "f"(d) : "memory");
}
__device__ __forceinline__ unsigned ld_acq(const unsigned* p) {
    unsigned v;
    asm volatile("ld.acquire.gpu.global.u32 %0, [%1];"
                 : "=r"(v) : "l"(p) : "memory");
    return v;
}
__device__ __forceinline__ void arrive_release(unsigned* p) {
    asm volatile("red.release.gpu.global.add.u32 [%0], 1;"
                 :: "l"(p) : "memory");
}

// ---------------------------------------------------------------------------
// Kernel 1: C[m][n] = sum_k A[m][k]*W[n][k] + b_ih[n] + b_hh[n]   (FFMA2)
// Tile 64x64x16, 128 threads, thread tile 8m x 4n (m paired for f32x2).
// ---------------------------------------------------------------------------
__global__ __launch_bounds__(128) void gemm_xw_kernel(
    const float* __restrict__ A,
    const float* __restrict__ W,
    const float* __restrict__ b_ih,
    const float* __restrict__ b_hh,
    float* __restrict__ C)
{
    __shared__ float sA[16][68];   // [k][m]
    __shared__ float sB[16][68];   // [k][n]

    const int t  = threadIdx.x;
    const int n0 = blockIdx.x * 64;
    const int m0 = blockIdx.y * 64;
    const int tx = t & 15;
    const int ty = t >> 4;
    const int lr = t >> 1;
    const int lk = (t & 1) * 8;

    ull acc[4][4];
#pragma unroll
    for (int i = 0; i < 4; ++i)
#pragma unroll
        for (int j = 0; j < 4; ++j) acc[i][j] = 0ull;

    const float* Arow = A + (size_t)(m0 + lr) * INP + lk;
    const float* Wrow = W + (size_t)(n0 + lr) * INP + lk;

    for (int k0 = 0; k0 < INP; k0 += 16) {
        float4 a0 = *(const float4*)(Arow + k0);
        float4 a1 = *(const float4*)(Arow + k0 + 4);
        float4 w0 = *(const float4*)(Wrow + k0);
        float4 w1 = *(const float4*)(Wrow + k0 + 4);
        __syncthreads();
        sA[lk + 0][lr] = a0.x; sA[lk + 1][lr] = a0.y;
        sA[lk + 2][lr] = a0.z; sA[lk + 3][lr] = a0.w;
        sA[lk + 4][lr] = a1.x; sA[lk + 5][lr] = a1.y;
        sA[lk + 6][lr] = a1.z; sA[lk + 7][lr] = a1.w;
        sB[lk + 0][lr] = w0.x; sB[lk + 1][lr] = w0.y;
        sB[lk + 2][lr] = w0.z; sB[lk + 3][lr] = w0.w;
        sB[lk + 4][lr] = w1.x; sB[lk + 5][lr] = w1.y;
        sB[lk + 6][lr] = w1.z; sB[lk + 7][lr] = w1.w;
        __syncthreads();
#pragma unroll
        for (int k = 0; k < 16; ++k) {
            const ull* arow = (const ull*)&sA[k][ty * 8];
            ull am0 = arow[0], am1 = arow[1], am2 = arow[2], am3 = arow[3];
            float4 bv = *(const float4*)&sB[k][tx * 4];
            ull bn0 = dup2(bv.x), bn1 = dup2(bv.y);
            ull bn2 = dup2(bv.z), bn3 = dup2(bv.w);
            acc[0][0] = ffma2(am0, bn0, acc[0][0]);
            acc[0][1] = ffma2(am0, bn1, acc[0][1]);
            acc[0][2] = ffma2(am0, bn2, acc[0][2]);
            acc[0][3] = ffma2(am0, bn3, acc[0][3]);
            acc[1][0] = ffma2(am1, bn0, acc[1][0]);
            acc[1][1] = ffma2(am1, bn1, acc[1][1]);
            acc[1][2] = ffma2(am1, bn2, acc[1][2]);
            acc[1][3] = ffma2(am1, bn3, acc[1][3]);
            acc[2][0] = ffma2(am2, bn0, acc[2][0]);
            acc[2][1] = ffma2(am2, bn1, acc[2][1]);
            acc[2][2] = ffma2(am2, bn2, acc[2][2]);
            acc[2][3] = ffma2(am2, bn3, acc[2][3]);
            acc[3][0] = ffma2(am3, bn0, acc[3][0]);
            acc[3][1] = ffma2(am3, bn1, acc[3][1]);
            acc[3][2] = ffma2(am3, bn2, acc[3][2]);
            acc[3][3] = ffma2(am3, bn3, acc[3][3]);
        }
    }

    float4 bi = *(const float4*)(b_ih + n0 + tx * 4);
    float4 bh = *(const float4*)(b_hh + n0 + tx * 4);
    float4 bias;
    bias.x = bi.x + bh.x; bias.y = bi.y + bh.y;
    bias.z = bi.z + bh.z; bias.w = bi.w + bh.w;

#pragma unroll
    for (int i = 0; i < 8; ++i) {
        const int mp = i >> 1;
        const int sel = i & 1;
        float2 a0 = *(float2*)&acc[mp][0];
        float2 a1 = *(float2*)&acc[mp][1];
        float2 a2 = *(float2*)&acc[mp][2];
        float2 a3 = *(float2*)&acc[mp][3];
        float4 o;
        o.x = (sel ? a0.y : a0.x) + bias.x;
        o.y = (sel ? a1.y : a1.x) + bias.y;
        o.z = (sel ? a2.y : a2.x) + bias.z;
        o.w = (sel ? a3.y : a3.x) + bias.w;
        *(float4*)&C[(size_t)(m0 + ty * 8 + i) * HID + n0 + tx * 4] = o;
    }
}

// ---------------------------------------------------------------------------
// Kernel 2: persistent recurrence. 256 threads (2 warps/SMSP).
// CTA (jc,kc): W_hh[jc*64..+64) x [kc*128..+128) cached in smem (k-major).
// Thread tile 2b x 8j (j paired for f32x2; W pairs natural). No k-split.
// ---------------------------------------------------------------------------
__global__ __launch_bounds__(256) void rnn_step_kernel(
    const float* __restrict__ Whh,   // 1024 x 1024
    float* __restrict__ out)         // (64, 512, 1024) pre-seeded with xw+bias
{
    extern __shared__ float smem[];
    float* sW = smem;                      // [128][SW_STRIDE]
    float* sh = smem + 128 * SW_STRIDE;    // [128][SH_STRIDE]

    const int t  = threadIdx.x;
    const int jc = blockIdx.x & 15;   // 0..15 (64 j each)
    const int kc = blockIdx.x >> 4;   // 0..7  (128 k each)

    // One-time W tile load, transposed to k-major.
    {
        const int j  = t >> 2;              // 0..63
        const int kq = (t & 3) * 32;        // 0,32,64,96
        const float* src = Whh + (size_t)(jc * 64 + j) * HID + kc * 128 + kq;
#pragma unroll
        for (int kk = 0; kk < 32; kk += 4) {
            float4 v = *(const float4*)(src + kk);
            sW[(kq + kk + 0) * SW_STRIDE + j] = v.x;
            sW[(kq + kk + 1) * SW_STRIDE + j] = v.y;
            sW[(kq + kk + 2) * SW_STRIDE + j] = v.z;
            sW[(kq + kk + 3) * SW_STRIDE + j] = v.w;
        }
    }
    __syncthreads();

    const int tb2 = (t & 31) * 2;     // base b of thread tile (2 b)
    const int tj8 = (t >> 5) * 8;     // base j of thread tile (4 j-pairs)
    const int fb  = t & 63;           // fill: b row
    const int fk  = (t >> 6) * 32;    // fill: k base (32 k per thread)

    for (int s = 1; s < SEQ; ++s) {
        if (s >= 2) {
            if (t == 0) {
                const unsigned* p = &g_cnt[s - 1];
                while (ld_acq(p) != (unsigned)NCTA) __nanosleep(8);
            }
            __syncthreads();
        }

        // Fill sh[k][b] = tanh(pre-act[b][s-1][kc*128+k]). Conflict-free STS.
        {
            const float* src = out + ((size_t)(fb * SEQ + (s - 1))) * HID
                                   + kc * 128 + fk;
#pragma unroll
            for (int kk = 0; kk < 32; kk += 4) {
                float4 v = __ldcg((const float4*)(src + kk));
                sh[(fk + kk + 0) * SH_STRIDE + fb] = tanhf(v.x);
                sh[(fk + kk + 1) * SH_STRIDE + fb] = tanhf(v.y);
                sh[(fk + kk + 2) * SH_STRIDE + fb] = tanhf(v.z);
                sh[(fk + kk + 3) * SH_STRIDE + fb] = tanhf(v.w);
            }
        }
        __syncthreads();

        ull acc[2][4];                 // [b][j-pair]
#pragma unroll
        for (int i = 0; i < 2; ++i)
#pragma unroll
            for (int j = 0; j < 4; ++j) acc[i][j] = 0ull;

        const float* hbase = sh + tb2;
        const float* wbase = sW + tj8;

#pragma unroll 8
        for (int k = 0; k < 128; ++k) {
            float2 hv = *(const float2*)(hbase + (size_t)k * SH_STRIDE);
            ulonglong2 wA = *(const ulonglong2*)(wbase + (size_t)k * SW_STRIDE);
            ulonglong2 wB = *(const ulonglong2*)(wbase + (size_t)k * SW_STRIDE + 4);
            ull h0 = dup2(hv.x), h1 = dup2(hv.y);
            acc[0][0] = ffma2(h0, wA.x, acc[0][0]);
            acc[0][1] = ffma2(h0, wA.y, acc[0][1]);
            acc[0][2] = ffma2(h0, wB.x, acc[0][2]);
            acc[0][3] = ffma2(h0, wB.y, acc[0][3]);
            acc[1][0] = ffma2(h1, wA.x, acc[1][0]);
            acc[1][1] = ffma2(h1, wA.y, acc[1][1]);
            acc[1][2] = ffma2(h1, wB.x, acc[1][2]);
            acc[1][3] = ffma2(h1, wB.y, acc[1][3]);
        }

        // Vectorized reduction into the pre-act buffer for step s.
#pragma unroll
        for (int i = 0; i < 2; ++i) {
            const int b = tb2 + i;
            float* row = out + ((size_t)(b * SEQ + s)) * HID + jc * 64 + tj8;
            float2 a0 = *(float2*)&acc[i][0];
            float2 a1 = *(float2*)&acc[i][1];
            float2 a2 = *(float2*)&acc[i][2];
            float2 a3 = *(float2*)&acc[i][3];
            red_add_v4(row,     a0.x, a0.y, a1.x, a1.y);
            red_add_v4(row + 4, a2.x, a2.y, a3.x, a3.y);
        }

        // bar.sync orders all threads' red ops before t0's release-arrive.
        __syncthreads();
        if (t == 0 && s < SEQ - 1) arrive_release(&g_cnt[s]);
    }
}

// ---------------------------------------------------------------------------
// Kernel 3: elementwise tanh over the whole output buffer.
// ---------------------------------------------------------------------------
__global__ __launch_bounds__(256) void tanh_kernel(float* __restrict__ out) {
    size_t i = ((size_t)blockIdx.x * blockDim.x + threadIdx.x) * 4;
    float4 v = *(float4*)(out + i);
    v.x = tanhf(v.x); v.y = tanhf(v.y);
    v.z = tanhf(v.z); v.w = tanhf(v.w);
    *(float4*)(out + i) = v;
}

extern "C" void kernel_launch(void* const* d_in, const int* in_sizes, int n_in,
                              void* d_out, int out_size) {
    const float* x   = (const float*)d_in[0];   // (64, 512, 512)
    const float* Wih = (const float*)d_in[1];   // (1024, 512)
    const float* Whh = (const float*)d_in[2];   // (1024, 1024)
    const float* bih = (const float*)d_in[3];   // (1024,)
    const float* bhh = (const float*)d_in[4];   // (1024,)
    float* out = (float*)d_out;                 // (64, 512, 1024)

    cudaFuncSetAttribute(rnn_step_kernel,
                         cudaFuncAttributeMaxDynamicSharedMemorySize, SMEM2);

    zero_cnt_kernel<<<1, SEQ>>>();

    dim3 g1(HID / 64, (BSZ * SEQ) / 64);
    gemm_xw_kernel<<<g1, 128>>>(x, Wih, bih, bhh, out);

    rnn_step_kernel<<<NCTA, 256, SMEM2>>>(Whh, out);

    tanh_kernel<<<(BSZ * SEQ * HID) / (256 * 4), 256>>>(out);
}